// round 16
// baseline (speedup 1.0000x reference)
#include <cuda_runtime.h>
#include <cuda_fp16.h>
#include <cstdint>

#define NB 2
#define NN 8192
#define BM 64
#define NTILES 64
#define L2E 1.4426950408889634f

// -------- scratch (device globals; no allocation allowed) --------
__device__ __align__(16) __half g_Qh[NB][NN][16];  // fp16 Q, pre-scaled by log2e (A side)
__device__ __align__(16) __half g_Kh[NB][NN][16];  // fp16 K, unscaled (B side)
__device__ __align__(16) __half g_Vh[NB][NN][32];  // fp16 V
__device__ float g_Rn[NB][NN];                     // |Q_i|^2 (fp32, unscaled)
__device__ float g_bmax[NB][256];                  // per-block max |Q|^2
__device__ unsigned g_barrier;                     // grid barrier epoch counter (monotonic)

// ---------------- helpers ----------------
__device__ __forceinline__ uint32_t smem_u32(const void* p) {
    uint32_t a;
    asm("{ .reg .u64 t; cvta.to.shared.u64 t, %1; cvt.u32.u64 %0, t; }" : "=r"(a) : "l"(p));
    return a;
}
__device__ __forceinline__ void ldsm4(uint32_t* r, uint32_t a) {
    asm volatile("ldmatrix.sync.aligned.m8n8.x4.shared.b16 {%0,%1,%2,%3}, [%4];"
        : "=r"(r[0]), "=r"(r[1]), "=r"(r[2]), "=r"(r[3]) : "r"(a));
}
__device__ __forceinline__ void ldsm4t(uint32_t* r, uint32_t a) {
    asm volatile("ldmatrix.sync.aligned.m8n8.x4.trans.shared.b16 {%0,%1,%2,%3}, [%4];"
        : "=r"(r[0]), "=r"(r[1]), "=r"(r[2]), "=r"(r[3]) : "r"(a));
}
// f16-accumulate MMA — D layout == next A-fragment layout
__device__ __forceinline__ void mma16816h(uint32_t* d, const uint32_t* a, uint32_t b0, uint32_t b1,
                                          uint32_t c0, uint32_t c1) {
    asm volatile("mma.sync.aligned.m16n8k16.row.col.f16.f16.f16.f16 "
        "{%0,%1}, {%2,%3,%4,%5}, {%6,%7}, {%8,%9};"
        : "=r"(d[0]), "=r"(d[1])
        : "r"(a[0]), "r"(a[1]), "r"(a[2]), "r"(a[3]), "r"(b0), "r"(b1), "r"(c0), "r"(c1));
}
// m16n8k8 f32-accumulate converter: D += A * B (B = identity -> f16->f32 transfer)
__device__ __forceinline__ void mmacv(float* d, const uint32_t* a, uint32_t b) {
    asm volatile("mma.sync.aligned.m16n8k8.row.col.f32.f16.f16.f32 "
        "{%0,%1,%2,%3}, {%4,%5}, {%6}, {%0,%1,%2,%3};"
        : "+f"(d[0]), "+f"(d[1]), "+f"(d[2]), "+f"(d[3])
        : "r"(a[0]), "r"(a[1]), "r"(b));
}
__device__ __forceinline__ uint32_t ex2h(uint32_t x) {
    uint32_t r; asm("ex2.approx.f16x2 %0, %1;" : "=r"(r) : "r"(x)); return r;
}
__device__ __forceinline__ uint32_t packh2(float a, float b) {
    __half2 h = __floats2half2_rn(a, b);
    return *(uint32_t*)&h;
}
__device__ __forceinline__ void cp16(uint32_t dst, const void* src) {
    asm volatile("cp.async.ca.shared.global [%0], [%1], 16;" :: "r"(dst), "l"(src));
}
#define CP_COMMIT() asm volatile("cp.async.commit_group;" ::: "memory")
#define CP_WAIT1()  asm volatile("cp.async.wait_group 1;" ::: "memory")
#define CP_WAIT0()  asm volatile("cp.async.wait_group 0;" ::: "memory")

#define ONE2 0x3C003C00u   // half2 {1.0, 1.0}

// ---- smem arena ----
#define SQ_OFF   0            // Q: 2 KB
#define SK_OFF   2048         // K: 3 x 4 KB
#define SV_OFF   14336        // V: 3 x 8 KB
#define SRED_OFF 38912        // 8 floats
#define SM_BYTES 38944

// ======== fused kernel: qv phase -> grid barrier -> attn phase ========
// Grid MUST be 256 CTAs with >=2 CTAs/SM residency (148*2=296>256) for the spin barrier.
__global__ void __launch_bounds__(256, 2) fused_kernel(
    const float* __restrict__ inp, const float* __restrict__ W1,
    const float* __restrict__ b1,  const float* __restrict__ W2,
    const float* __restrict__ b2,  const float* __restrict__ gamma,
    float* __restrict__ out)
{
    __shared__ __align__(16) char sm[SM_BYTES];

    int tid = threadIdx.x, lane = tid & 31, wid = tid >> 5;
    int flat = blockIdx.x + (int)gridDim.x * blockIdx.y;   // 0..255

    // ================= qv phase: 2 (b,hw) columns per CTA =================
    {
        float (*Xs)[32]  = (float(*)[32])(sm + 0);
        float (*W1s)[32] = (float(*)[32])(sm + 4096);
        float (*W2s)[32] = (float(*)[32])(sm + 6144);
        float* b1s = (float*)(sm + 10240);
        float* b2s = (float*)(sm + 10304);
        float (*Aq)[16]  = (float(*)[16])(sm + 10432);

        for (int idx = tid; idx < 512;  idx += 256) W1s[idx >> 5][idx & 31] = W1[idx];
        for (int idx = tid; idx < 1024; idx += 256) W2s[idx >> 5][idx & 31] = W2[idx];
        if (tid < 16) b1s[tid] = b1[tid];
        if (tid >= 32 && tid < 64) b2s[tid - 32] = b2[tid - 32];

        #pragma unroll 1
        for (int p = 0; p < 2; p++) {
            int q = flat * 2 + p;
            int b = q >> 8, hw = q & 255;
            __syncthreads();
            const float* ib = inp + (size_t)b * 262144 + hw * 32;
            for (int idx = tid; idx < 1024; idx += 256) {
                int l = idx >> 5, c = idx & 31;
                Xs[l][c] = ib[l * 8192 + c];
            }
            __syncthreads();

            for (int idx = tid; idx < 1024; idx += 256) {
                int o = idx >> 5, c = idx & 31;
                float s = b2s[o];
                #pragma unroll
                for (int l = 0; l < 32; l++) s += W2s[o][l] * Xs[l][c];
                g_Vh[b][o * 256 + hw][c] = __float2half(s);
            }
            for (int idx = tid; idx < 512; idx += 256) {
                int o = idx >> 5, ch = idx & 31;
                float s = b1s[o];
                #pragma unroll
                for (int l = 0; l < 32; l++) s += W1s[o][l] * Xs[l][ch];
                int k = ch >> 1, i12 = ch & 1;
                int row = i12 * 4096 + o * 256 + hw;
                g_Qh[b][row][k] = __float2half(s * L2E);
                g_Kh[b][row][k] = __float2half(s);
                Aq[(o << 1) | i12][k] = s;
            }
            __syncthreads();

            if (tid < 32) {
                int o = tid >> 1, i12 = tid & 1;
                float s = 0.f;
                #pragma unroll
                for (int k = 0; k < 16; k++) { float v = Aq[tid][k]; s += v * v; }
                g_Rn[b][i12 * 4096 + o * 256 + hw] = s;
                float m = s;
                #pragma unroll
                for (int off = 16; off; off >>= 1)
                    m = fmaxf(m, __shfl_xor_sync(0xffffffffu, m, off));
                if (tid == 0) g_bmax[b][hw] = m;
            }
        }
    }

    // ================= grid-wide barrier =================
    __threadfence();
    __syncthreads();
    if (tid == 0) {
        unsigned old = atomicAdd(&g_barrier, 1u);
        unsigned target = ((old >> 8) + 1u) << 8;
        for (;;) {
            unsigned v;
            asm volatile("ld.volatile.global.u32 %0, [%1];" : "=r"(v) : "l"(&g_barrier));
            if (v >= target) break;
            __nanosleep(64);
        }
    }
    __syncthreads();

    // ================= attn phase =================
    int rh = wid & 1, g = wid >> 1;
    int b = blockIdx.y;
    int i0 = blockIdx.x * BM;

    uint32_t sb = smem_u32(sm);
    float* red = (float*)(sm + SRED_OFF);

    const int kr = tid >> 1, ks = tid & 1;
    const uint32_t koff = kr * 32 + (ks ^ ((kr >> 2) & 1)) * 16;
    const int vr0 = tid >> 2, vs0 = tid & 3;
    const int e1 = tid + 256, vr1 = e1 >> 2, vs1 = e1 & 3;
    const uint32_t voff0 = vr0 * 64 + (vs0 ^ ((vr0 >> 1) & 3)) * 16;
    const uint32_t voff1 = vr1 * 64 + (vs1 ^ ((vr1 >> 1) & 3)) * 16;

    float mv = g_bmax[b][tid];
    {
        cp16(sb + SK_OFF + koff, &g_Kh[b][kr][ks * 8]);
        cp16(sb + SV_OFF + voff0, &g_Vh[b][vr0][vs0 * 8]);
        cp16(sb + SV_OFF + voff1, &g_Vh[b][vr1][vs1 * 8]);
        CP_COMMIT();
        cp16(sb + SK_OFF + 4096 + koff, &g_Kh[b][128 + kr][ks * 8]);
        cp16(sb + SV_OFF + 8192 + voff0, &g_Vh[b][128 + vr0][vs0 * 8]);
        cp16(sb + SV_OFF + 8192 + voff1, &g_Vh[b][128 + vr1][vs1 * 8]);
        CP_COMMIT();
    }
    if (tid < 128) {
        int r = tid >> 1, s = tid & 1;
        ((uint4*)(sm + SQ_OFF))[r * 2 + (s ^ ((r >> 2) & 1))] =
            *(const uint4*)&g_Qh[b][i0 + r][s * 8];
    }
    #pragma unroll
    for (int off = 16; off; off >>= 1)
        mv = fmaxf(mv, __shfl_xor_sync(0xffffffffu, mv, off));
    if (lane == 0) red[wid] = mv;
    __syncthreads();

    float msq = red[0];
    #pragma unroll
    for (int w = 1; w < 8; w++) msq = fmaxf(msq, red[w]);

    uint32_t qa[2][4];
    #pragma unroll
    for (int fr = 0; fr < 2; fr++) {
        int row = rh * 32 + fr * 16 + (lane & 7) + (lane & 8);
        int seg = lane >> 4;
        ldsm4(qa[fr], sb + SQ_OFF + row * 32 + (seg ^ ((row >> 2) & 1)) * 16);
    }

    uint32_t mch[2][2];
    #pragma unroll
    for (int fr = 0; fr < 2; fr++) {
        int ia = i0 + rh * 32 + fr * 16 + (lane >> 2);
        float m0 = L2E * sqrtf(g_Rn[b][ia] * msq);
        float m1 = L2E * sqrtf(g_Rn[b][ia + 8] * msq);
        mch[fr][0] = packh2(-m0, -m0);
        mch[fr][1] = packh2(-m1, -m1);
    }

    // identity B-fragment for the m16n8k8 f16->f32 converter:
    // B[k][n] = delta(k,n); lane holds k = (lane&3)*2 (lo), +1 (hi); n = lane>>2
    uint32_t ident;
    {
        int n = lane >> 2, k0 = (lane & 3) * 2;
        ident = ((k0 == n) ? 0x3C00u : 0u) | ((k0 + 1 == n) ? 0x3C000000u : 0u);
    }

    float Dc[2][16];
    float la[2], lb[2];
    #pragma unroll
    for (int fr = 0; fr < 2; fr++) {
        #pragma unroll
        for (int q = 0; q < 16; q++) Dc[fr][q] = 0.f;
        la[fr] = 0.f; lb[fr] = 0.f;
    }

    uint32_t kfo[2], vfo0[2], vfo1[2];
    #pragma unroll
    for (int np = 0; np < 2; np++) {
        int row = (g * 2 + np) * 16 + (lane & 7) + ((lane >> 4) << 3);
        int seg = (lane >> 3) & 1;
        kfo[np] = row * 32 + (seg ^ ((row >> 2) & 1)) * 16;
        int vrow = (g * 2 + np) * 16 + (lane & 7) + (((lane >> 3) & 1) << 3);
        int vseg = (lane >> 4) & 1;
        vfo0[np] = vrow * 64 + ((vseg)     ^ ((vrow >> 1) & 3)) * 16;
        vfo1[np] = vrow * 64 + ((vseg + 2) ^ ((vrow >> 1) & 3)) * 16;
    }

    // ---- tile body (buf is compile-time at each call site via unroll-by-3) ----
    auto tile_body = [&](int t, int buf) {
        if (t < NTILES - 1) CP_WAIT1(); else CP_WAIT0();
        __syncthreads();

        if (t < NTILES - 2) {
            int nxt2 = buf + 2; if (nxt2 >= 3) nxt2 -= 3;
            int jb2 = (t + 2) * 128;
            cp16(sb + SK_OFF + nxt2 * 4096 + koff, &g_Kh[b][jb2 + kr][ks * 8]);
            cp16(sb + SV_OFF + nxt2 * 8192 + voff0, &g_Vh[b][jb2 + vr0][vs0 * 8]);
            cp16(sb + SV_OFF + nxt2 * 8192 + voff1, &g_Vh[b][jb2 + vr1][vs1 * 8]);
            CP_COMMIT();
        }

        uint32_t kb = sb + SK_OFF + buf * 4096;
        uint32_t vb = sb + SV_OFF + buf * 8192;

        uint32_t pvh[2][4][2];   // per-tile f16 PV accumulators (chained over np)
        uint32_t dlh[2][2];      // per-tile f16 row-sum accumulators

        #pragma unroll
        for (int np = 0; np < 2; np++) {
            uint32_t kf[4];
            ldsm4(kf, kb + kfo[np]);
            uint32_t vf0[4], vf1[4];
            ldsm4t(vf0, vb + vfo0[np]);
            ldsm4t(vf1, vb + vfo1[np]);
            #pragma unroll
            for (int fr = 0; fr < 2; fr++) {
                uint32_t s0[2], s1[2];
                mma16816h(s0, qa[fr], kf[0], kf[1], mch[fr][0], mch[fr][1]);
                mma16816h(s1, qa[fr], kf[2], kf[3], mch[fr][0], mch[fr][1]);

                uint32_t pA[4];
                pA[0] = ex2h(s0[0]);
                pA[1] = ex2h(s0[1]);
                pA[2] = ex2h(s1[0]);
                pA[3] = ex2h(s1[1]);

                uint32_t c0 = np ? dlh[fr][0] : 0u, c1 = np ? dlh[fr][1] : 0u;
                mma16816h(dlh[fr], pA, ONE2, ONE2, c0, c1);

                uint32_t z0 = np ? pvh[fr][0][0] : 0u, z1 = np ? pvh[fr][0][1] : 0u;
                mma16816h(pvh[fr][0], pA, vf0[0], vf0[1], z0, z1);
                z0 = np ? pvh[fr][1][0] : 0u; z1 = np ? pvh[fr][1][1] : 0u;
                mma16816h(pvh[fr][1], pA, vf0[2], vf0[3], z0, z1);
                z0 = np ? pvh[fr][2][0] : 0u; z1 = np ? pvh[fr][2][1] : 0u;
                mma16816h(pvh[fr][2], pA, vf1[0], vf1[1], z0, z1);
                z0 = np ? pvh[fr][3][0] : 0u; z1 = np ? pvh[fr][3][1] : 0u;
                mma16816h(pvh[fr][3], pA, vf1[2], vf1[3], z0, z1);
            }
        }

        // per-tile transfer: f16 -> f32 accumulators (tensor-pipe converter MMAs)
        #pragma unroll
        for (int fr = 0; fr < 2; fr++) {
            mmacv(Dc[fr] + 0,  pvh[fr][0], ident);
            mmacv(Dc[fr] + 4,  pvh[fr][1], ident);
            mmacv(Dc[fr] + 8,  pvh[fr][2], ident);
            mmacv(Dc[fr] + 12, pvh[fr][3], ident);
            __half2 h0 = *(__half2*)&dlh[fr][0];
            __half2 h1 = *(__half2*)&dlh[fr][1];
            la[fr] += __low2float(h0);
            lb[fr] += __low2float(h1);
        }
    };

    for (int tt = 0; tt < NTILES - 1; tt += 3) {
        tile_body(tt, 0);
        tile_body(tt + 1, 1);
        tile_body(tt + 2, 2);
    }
    tile_body(NTILES - 1, 0);   // 63 % 3 == 0

    // ---- combine the 4 j-groups' partials ----
    __syncthreads();
    float* scr = (float*)sm;
    if (g > 0) {
        float* p = scr + (((g - 1) * 2 + rh) * 32 + lane) * 37;
        #pragma unroll
        for (int fr = 0; fr < 2; fr++) {
            #pragma unroll
            for (int q = 0; q < 16; q++) p[fr * 16 + q] = Dc[fr][q];
        }
        p[32] = la[0]; p[33] = lb[0];
        p[34] = la[1]; p[35] = lb[1];
    }
    __syncthreads();

    if (g == 0) {
        #pragma unroll
        for (int gg = 0; gg < 3; gg++) {
            const float* p = scr + ((gg * 2 + rh) * 32 + lane) * 37;
            #pragma unroll
            for (int fr = 0; fr < 2; fr++) {
                #pragma unroll
                for (int q = 0; q < 16; q++) Dc[fr][q] += p[fr * 16 + q];
            }
            la[0] += p[32]; lb[0] += p[33];
            la[1] += p[34]; lb[1] += p[35];
        }

        float gm = gamma[0];
        #pragma unroll
        for (int fr = 0; fr < 2; fr++) {
            float ra = gm / la[fr], rb = gm / lb[fr];
            int ia = i0 + rh * 32 + fr * 16 + (lane >> 2);
            size_t ba = (size_t)b * 262144 + (size_t)ia * 32;
            size_t bb = ba + 8 * 32;
            #pragma unroll
            for (int nt = 0; nt < 4; nt++) {
                int col = nt * 8 + (lane & 3) * 2;
                float2 iv = *(const float2*)(inp + ba + col);
                float2 ov;
                ov.x = Dc[fr][nt * 4 + 0] * ra + iv.x;
                ov.y = Dc[fr][nt * 4 + 1] * ra + iv.y;
                *(float2*)(out + ba + col) = ov;
                iv = *(const float2*)(inp + bb + col);
                ov.x = Dc[fr][nt * 4 + 2] * rb + iv.x;
                ov.y = Dc[fr][nt * 4 + 3] * rb + iv.y;
                *(float2*)(out + bb + col) = ov;
            }
        }
    }
}

extern "C" void kernel_launch(void* const* d_in, const int* in_sizes, int n_in,
                              void* d_out, int out_size) {
    const float* inp   = (const float*)d_in[0];
    const float* W1    = (const float*)d_in[1];
    const float* b1    = (const float*)d_in[2];
    const float* W2    = (const float*)d_in[3];
    const float* b2    = (const float*)d_in[4];
    const float* gamma = (const float*)d_in[5];
    float* out = (float*)d_out;

    fused_kernel<<<dim3(NN / BM, NB), 256>>>(inp, W1, b1, W2, b2, gamma, out);
}

// round 17
// speedup vs baseline: 1.0246x; 1.0246x over previous
#include <cuda_runtime.h>
#include <cuda_fp16.h>
#include <cstdint>

#define NB 2
#define NN 8192
#define BM 64
#define NTILES 64
#define L2E 1.4426950408889634f

// -------- scratch (device globals; no allocation allowed) --------
__device__ __align__(16) __half g_Qh[NB][NN][16];  // fp16 Q, pre-scaled by log2e (A side)
__device__ __align__(16) __half g_Kh[NB][NN][16];  // fp16 K, unscaled (B side)
__device__ __align__(16) __half g_Vh[NB][NN][32];  // fp16 V
__device__ float g_Rn[NB][NN];                     // |Q_i|^2 (fp32, unscaled)
__device__ float g_bmax[NB][256];                  // per-block max |Q|^2
__device__ unsigned g_barrier;                     // grid barrier epoch counter (monotonic)

// ---------------- helpers ----------------
__device__ __forceinline__ uint32_t smem_u32(const void* p) {
    uint32_t a;
    asm("{ .reg .u64 t; cvta.to.shared.u64 t, %1; cvt.u32.u64 %0, t; }" : "=r"(a) : "l"(p));
    return a;
}
__device__ __forceinline__ void ldsm4(uint32_t* r, uint32_t a) {
    asm volatile("ldmatrix.sync.aligned.m8n8.x4.shared.b16 {%0,%1,%2,%3}, [%4];"
        : "=r"(r[0]), "=r"(r[1]), "=r"(r[2]), "=r"(r[3]) : "r"(a));
}
__device__ __forceinline__ void ldsm4t(uint32_t* r, uint32_t a) {
    asm volatile("ldmatrix.sync.aligned.m8n8.x4.trans.shared.b16 {%0,%1,%2,%3}, [%4];"
        : "=r"(r[0]), "=r"(r[1]), "=r"(r[2]), "=r"(r[3]) : "r"(a));
}
// f16-accumulate MMA — D layout == next A-fragment layout
__device__ __forceinline__ void mma16816h(uint32_t* d, const uint32_t* a, uint32_t b0, uint32_t b1,
                                          uint32_t c0, uint32_t c1) {
    asm volatile("mma.sync.aligned.m16n8k16.row.col.f16.f16.f16.f16 "
        "{%0,%1}, {%2,%3,%4,%5}, {%6,%7}, {%8,%9};"
        : "=r"(d[0]), "=r"(d[1])
        : "r"(a[0]), "r"(a[1]), "r"(a[2]), "r"(a[3]), "r"(b0), "r"(b1), "r"(c0), "r"(c1));
}
// m16n8k8 f32-accumulate converter: D += A * B (B = identity -> f16->f32 transfer)
__device__ __forceinline__ void mmacv(float* d, const uint32_t* a, uint32_t b) {
    asm volatile("mma.sync.aligned.m16n8k8.row.col.f32.f16.f16.f32 "
        "{%0,%1,%2,%3}, {%4,%5}, {%6}, {%0,%1,%2,%3};"
        : "+f"(d[0]), "+f"(d[1]), "+f"(d[2]), "+f"(d[3])
        : "r"(a[0]), "r"(a[1]), "r"(b));
}
__device__ __forceinline__ uint32_t ex2h(uint32_t x) {
    uint32_t r; asm("ex2.approx.f16x2 %0, %1;" : "=r"(r) : "r"(x)); return r;
}
__device__ __forceinline__ uint32_t packh2(float a, float b) {
    __half2 h = __floats2half2_rn(a, b);
    return *(uint32_t*)&h;
}
__device__ __forceinline__ void cp16(uint32_t dst, const void* src) {
    asm volatile("cp.async.ca.shared.global [%0], [%1], 16;" :: "r"(dst), "l"(src));
}
#define CP_COMMIT() asm volatile("cp.async.commit_group;" ::: "memory")
#define CP_WAIT1()  asm volatile("cp.async.wait_group 1;" ::: "memory")
#define CP_WAIT0()  asm volatile("cp.async.wait_group 0;" ::: "memory")

#define ONE2 0x3C003C00u   // half2 {1.0, 1.0}

// ---- smem arena ----
#define SQ_OFF   0            // Q: 2 KB
#define SK_OFF   2048         // K: 3 x 4 KB
#define SV_OFF   14336        // V: 3 x 8 KB
#define SRED_OFF 38912        // 8 floats
#define SM_BYTES 38944

// ======== fused kernel: qv phase -> grid barrier -> attn phase ========
// Grid MUST be 256 CTAs with >=2 CTAs/SM residency (148*2=296>256) for the spin barrier.
__global__ void __launch_bounds__(256, 2) fused_kernel(
    const float* __restrict__ inp, const float* __restrict__ W1,
    const float* __restrict__ b1,  const float* __restrict__ W2,
    const float* __restrict__ b2,  const float* __restrict__ gamma,
    float* __restrict__ out)
{
    __shared__ __align__(16) char sm[SM_BYTES];

    int tid = threadIdx.x, lane = tid & 31, wid = tid >> 5;
    int flat = blockIdx.x + (int)gridDim.x * blockIdx.y;   // 0..255

    // ================= qv phase: 2 (b,hw) columns per CTA =================
    {
        float (*Xs)[32]  = (float(*)[32])(sm + 0);
        float (*W1s)[32] = (float(*)[32])(sm + 4096);
        float (*W2s)[32] = (float(*)[32])(sm + 6144);
        float* b1s = (float*)(sm + 10240);
        float* b2s = (float*)(sm + 10304);
        float (*Aq)[16]  = (float(*)[16])(sm + 10432);

        for (int idx = tid; idx < 512;  idx += 256) W1s[idx >> 5][idx & 31] = W1[idx];
        for (int idx = tid; idx < 1024; idx += 256) W2s[idx >> 5][idx & 31] = W2[idx];
        if (tid < 16) b1s[tid] = b1[tid];
        if (tid >= 32 && tid < 64) b2s[tid - 32] = b2[tid - 32];

        #pragma unroll 1
        for (int p = 0; p < 2; p++) {
            int q = flat * 2 + p;
            int b = q >> 8, hw = q & 255;
            __syncthreads();
            const float* ib = inp + (size_t)b * 262144 + hw * 32;
            for (int idx = tid; idx < 1024; idx += 256) {
                int l = idx >> 5, c = idx & 31;
                Xs[l][c] = ib[l * 8192 + c];
            }
            __syncthreads();

            for (int idx = tid; idx < 1024; idx += 256) {
                int o = idx >> 5, c = idx & 31;
                float s = b2s[o];
                #pragma unroll
                for (int l = 0; l < 32; l++) s += W2s[o][l] * Xs[l][c];
                g_Vh[b][o * 256 + hw][c] = __float2half(s);
            }
            for (int idx = tid; idx < 512; idx += 256) {
                int o = idx >> 5, ch = idx & 31;
                float s = b1s[o];
                #pragma unroll
                for (int l = 0; l < 32; l++) s += W1s[o][l] * Xs[l][ch];
                int k = ch >> 1, i12 = ch & 1;
                int row = i12 * 4096 + o * 256 + hw;
                g_Qh[b][row][k] = __float2half(s * L2E);
                g_Kh[b][row][k] = __float2half(s);
                Aq[(o << 1) | i12][k] = s;
            }
            __syncthreads();

            if (tid < 32) {
                int o = tid >> 1, i12 = tid & 1;
                float s = 0.f;
                #pragma unroll
                for (int k = 0; k < 16; k++) { float v = Aq[tid][k]; s += v * v; }
                g_Rn[b][i12 * 4096 + o * 256 + hw] = s;
                float m = s;
                #pragma unroll
                for (int off = 16; off; off >>= 1)
                    m = fmaxf(m, __shfl_xor_sync(0xffffffffu, m, off));
                if (tid == 0) g_bmax[b][hw] = m;
            }
        }
    }

    // ================= grid-wide barrier =================
    __threadfence();
    __syncthreads();
    if (tid == 0) {
        unsigned old = atomicAdd(&g_barrier, 1u);
        unsigned target = ((old >> 8) + 1u) << 8;
        for (;;) {
            unsigned v;
            asm volatile("ld.volatile.global.u32 %0, [%1];" : "=r"(v) : "l"(&g_barrier));
            if (v >= target) break;
            __nanosleep(64);
        }
    }
    __syncthreads();

    // ================= attn phase =================
    int rh = wid & 1, g = wid >> 1;
    int b = blockIdx.y;
    int i0 = blockIdx.x * BM;

    uint32_t sb = smem_u32(sm);
    float* red = (float*)(sm + SRED_OFF);

    const int kr = tid >> 1, ks = tid & 1;
    const uint32_t koff = kr * 32 + (ks ^ ((kr >> 2) & 1)) * 16;
    const int vr0 = tid >> 2, vs0 = tid & 3;
    const int e1 = tid + 256, vr1 = e1 >> 2, vs1 = e1 & 3;
    const uint32_t voff0 = vr0 * 64 + (vs0 ^ ((vr0 >> 1) & 3)) * 16;
    const uint32_t voff1 = vr1 * 64 + (vs1 ^ ((vr1 >> 1) & 3)) * 16;

    float mv = g_bmax[b][tid];
    {
        cp16(sb + SK_OFF + koff, &g_Kh[b][kr][ks * 8]);
        cp16(sb + SV_OFF + voff0, &g_Vh[b][vr0][vs0 * 8]);
        cp16(sb + SV_OFF + voff1, &g_Vh[b][vr1][vs1 * 8]);
        CP_COMMIT();
        cp16(sb + SK_OFF + 4096 + koff, &g_Kh[b][128 + kr][ks * 8]);
        cp16(sb + SV_OFF + 8192 + voff0, &g_Vh[b][128 + vr0][vs0 * 8]);
        cp16(sb + SV_OFF + 8192 + voff1, &g_Vh[b][128 + vr1][vs1 * 8]);
        CP_COMMIT();
    }
    if (tid < 128) {
        int r = tid >> 1, s = tid & 1;
        ((uint4*)(sm + SQ_OFF))[r * 2 + (s ^ ((r >> 2) & 1))] =
            *(const uint4*)&g_Qh[b][i0 + r][s * 8];
    }
    #pragma unroll
    for (int off = 16; off; off >>= 1)
        mv = fmaxf(mv, __shfl_xor_sync(0xffffffffu, mv, off));
    if (lane == 0) red[wid] = mv;
    __syncthreads();

    float msq = red[0];
    #pragma unroll
    for (int w = 1; w < 8; w++) msq = fmaxf(msq, red[w]);

    uint32_t qa[2][4];
    #pragma unroll
    for (int fr = 0; fr < 2; fr++) {
        int row = rh * 32 + fr * 16 + (lane & 7) + (lane & 8);
        int seg = lane >> 4;
        ldsm4(qa[fr], sb + SQ_OFF + row * 32 + (seg ^ ((row >> 2) & 1)) * 16);
    }

    uint32_t mch[2][2];
    #pragma unroll
    for (int fr = 0; fr < 2; fr++) {
        int ia = i0 + rh * 32 + fr * 16 + (lane >> 2);
        float m0 = L2E * sqrtf(g_Rn[b][ia] * msq);
        float m1 = L2E * sqrtf(g_Rn[b][ia + 8] * msq);
        mch[fr][0] = packh2(-m0, -m0);
        mch[fr][1] = packh2(-m1, -m1);
    }

    // identity B-fragment for the m16n8k8 f16->f32 converter:
    // B[k][n] = delta(k,n); lane holds k = (lane&3)*2 (lo), +1 (hi); n = lane>>2
    uint32_t ident;
    {
        int n = lane >> 2, k0 = (lane & 3) * 2;
        ident = ((k0 == n) ? 0x3C00u : 0u) | ((k0 + 1 == n) ? 0x3C000000u : 0u);
    }

    float Dc[2][16];
    float la[2], lb[2];
    #pragma unroll
    for (int fr = 0; fr < 2; fr++) {
        #pragma unroll
        for (int q = 0; q < 16; q++) Dc[fr][q] = 0.f;
        la[fr] = 0.f; lb[fr] = 0.f;
    }

    uint32_t kfo[2], vfo0[2], vfo1[2];
    #pragma unroll
    for (int np = 0; np < 2; np++) {
        int row = (g * 2 + np) * 16 + (lane & 7) + ((lane >> 4) << 3);
        int seg = (lane >> 3) & 1;
        kfo[np] = row * 32 + (seg ^ ((row >> 2) & 1)) * 16;
        int vrow = (g * 2 + np) * 16 + (lane & 7) + (((lane >> 3) & 1) << 3);
        int vseg = (lane >> 4) & 1;
        vfo0[np] = vrow * 64 + ((vseg)     ^ ((vrow >> 1) & 3)) * 16;
        vfo1[np] = vrow * 64 + ((vseg + 2) ^ ((vrow >> 1) & 3)) * 16;
    }

    // ---- tile body (buf is compile-time at each call site via unroll-by-3) ----
    auto tile_body = [&](int t, int buf) {
        if (t < NTILES - 1) CP_WAIT1(); else CP_WAIT0();
        __syncthreads();

        if (t < NTILES - 2) {
            int nxt2 = buf + 2; if (nxt2 >= 3) nxt2 -= 3;
            int jb2 = (t + 2) * 128;
            cp16(sb + SK_OFF + nxt2 * 4096 + koff, &g_Kh[b][jb2 + kr][ks * 8]);
            cp16(sb + SV_OFF + nxt2 * 8192 + voff0, &g_Vh[b][jb2 + vr0][vs0 * 8]);
            cp16(sb + SV_OFF + nxt2 * 8192 + voff1, &g_Vh[b][jb2 + vr1][vs1 * 8]);
            CP_COMMIT();
        }

        uint32_t kb = sb + SK_OFF + buf * 4096;
        uint32_t vb = sb + SV_OFF + buf * 8192;

        uint32_t pvh[2][4][2];   // per-tile f16 PV accumulators (chained over np)
        uint32_t dlh[2][2];      // per-tile f16 row-sum accumulators

        #pragma unroll
        for (int np = 0; np < 2; np++) {
            uint32_t kf[4];
            ldsm4(kf, kb + kfo[np]);
            uint32_t vf0[4], vf1[4];
            ldsm4t(vf0, vb + vfo0[np]);
            ldsm4t(vf1, vb + vfo1[np]);
            #pragma unroll
            for (int fr = 0; fr < 2; fr++) {
                uint32_t s0[2], s1[2];
                mma16816h(s0, qa[fr], kf[0], kf[1], mch[fr][0], mch[fr][1]);
                mma16816h(s1, qa[fr], kf[2], kf[3], mch[fr][0], mch[fr][1]);

                uint32_t pA[4];
                pA[0] = ex2h(s0[0]);
                pA[1] = ex2h(s0[1]);
                pA[2] = ex2h(s1[0]);
                pA[3] = ex2h(s1[1]);

                uint32_t c0 = np ? dlh[fr][0] : 0u, c1 = np ? dlh[fr][1] : 0u;
                mma16816h(dlh[fr], pA, ONE2, ONE2, c0, c1);

                uint32_t z0 = np ? pvh[fr][0][0] : 0u, z1 = np ? pvh[fr][0][1] : 0u;
                mma16816h(pvh[fr][0], pA, vf0[0], vf0[1], z0, z1);
                z0 = np ? pvh[fr][1][0] : 0u; z1 = np ? pvh[fr][1][1] : 0u;
                mma16816h(pvh[fr][1], pA, vf0[2], vf0[3], z0, z1);
                z0 = np ? pvh[fr][2][0] : 0u; z1 = np ? pvh[fr][2][1] : 0u;
                mma16816h(pvh[fr][2], pA, vf1[0], vf1[1], z0, z1);
                z0 = np ? pvh[fr][3][0] : 0u; z1 = np ? pvh[fr][3][1] : 0u;
                mma16816h(pvh[fr][3], pA, vf1[2], vf1[3], z0, z1);
            }
        }

        // per-tile transfer: f16 -> f32 accumulators (tensor-pipe converter MMAs)
        #pragma unroll
        for (int fr = 0; fr < 2; fr++) {
            mmacv(Dc[fr] + 0,  pvh[fr][0], ident);
            mmacv(Dc[fr] + 4,  pvh[fr][1], ident);
            mmacv(Dc[fr] + 8,  pvh[fr][2], ident);
            mmacv(Dc[fr] + 12, pvh[fr][3], ident);
            __half2 h0 = *(__half2*)&dlh[fr][0];
            __half2 h1 = *(__half2*)&dlh[fr][1];
            la[fr] += __low2float(h0);
            lb[fr] += __low2float(h1);
        }
    };

    for (int tt = 0; tt < NTILES - 1; tt += 3) {
        tile_body(tt, 0);
        tile_body(tt + 1, 1);
        tile_body(tt + 2, 2);
    }
    tile_body(NTILES - 1, 0);   // 63 % 3 == 0

    // ---- combine the 4 j-groups' partials ----
    __syncthreads();
    float* scr = (float*)sm;
    if (g > 0) {
        float* p = scr + (((g - 1) * 2 + rh) * 32 + lane) * 37;
        #pragma unroll
        for (int fr = 0; fr < 2; fr++) {
            #pragma unroll
            for (int q = 0; q < 16; q++) p[fr * 16 + q] = Dc[fr][q];
        }
        p[32] = la[0]; p[33] = lb[0];
        p[34] = la[1]; p[35] = lb[1];
    }
    __syncthreads();

    if (g == 0) {
        #pragma unroll
        for (int gg = 0; gg < 3; gg++) {
            const float* p = scr + ((gg * 2 + rh) * 32 + lane) * 37;
            #pragma unroll
            for (int fr = 0; fr < 2; fr++) {
                #pragma unroll
                for (int q = 0; q < 16; q++) Dc[fr][q] += p[fr * 16 + q];
            }
            la[0] += p[32]; lb[0] += p[33];
            la[1] += p[34]; lb[1] += p[35];
        }

        float gm = gamma[0];
        #pragma unroll
        for (int fr = 0; fr < 2; fr++) {
            float ra = gm / la[fr], rb = gm / lb[fr];
            int ia = i0 + rh * 32 + fr * 16 + (lane >> 2);
            size_t ba = (size_t)b * 262144 + (size_t)ia * 32;
            size_t bb = ba + 8 * 32;
            #pragma unroll
            for (int nt = 0; nt < 4; nt++) {
                int col = nt * 8 + (lane & 3) * 2;
                float2 iv = *(const float2*)(inp + ba + col);
                float2 ov;
                ov.x = Dc[fr][nt * 4 + 0] * ra + iv.x;
                ov.y = Dc[fr][nt * 4 + 1] * ra + iv.y;
                *(float2*)(out + ba + col) = ov;
                iv = *(const float2*)(inp + bb + col);
                ov.x = Dc[fr][nt * 4 + 2] * rb + iv.x;
                ov.y = Dc[fr][nt * 4 + 3] * rb + iv.y;
                *(float2*)(out + bb + col) = ov;
            }
        }
    }
}

extern "C" void kernel_launch(void* const* d_in, const int* in_sizes, int n_in,
                              void* d_out, int out_size) {
    const float* inp   = (const float*)d_in[0];
    const float* W1    = (const float*)d_in[1];
    const float* b1    = (const float*)d_in[2];
    const float* W2    = (const float*)d_in[3];
    const float* b2    = (const float*)d_in[4];
    const float* gamma = (const float*)d_in[5];
    float* out = (float*)d_out;

    fused_kernel<<<dim3(NN / BM, NB), 256>>>(inp, W1, b1, W2, b2, gamma, out);
}